// round 1
// baseline (speedup 1.0000x reference)
#include <cuda_runtime.h>
#include <cuda_bf16.h>
#include <math.h>

// Problem constants
#define B   256
#define S   512
#define D   768
#define D4  (D/4)        // 192 float4 per row
#define K4D 3072         // 4*D
#define H1  256
#define H2  64
#define L   4

// GEMM1 tiling
#define MT   16          // batch rows per block
#define KS   8           // split-K factor
#define KC   (K4D/KS)    // 384 k per split
#define KC4  (KC/4)      // 96 float4

// Scratch (device globals — no allocation allowed)
__device__ float g_f[B * K4D];            // features [256, 3072]  (3 MB)
__device__ float g_h1p[KS * B * H1];      // GEMM1 partials [8, 256, 256] (2 MB)

// ---------------------------------------------------------------------------
// K1: feature extraction. One block per batch sample, 192 threads (float4 lane)
// f[b] = [ CLS(x1) | mean(x1[s1:e1]) | CLS(x2) | mean(x2[s2:e2]) ]
// ---------------------------------------------------------------------------
__global__ void __launch_bounds__(D4) feat_kernel(
    const float* __restrict__ x1, const float* __restrict__ x2,
    const int* __restrict__ s1a, const int* __restrict__ e1a,
    const int* __restrict__ s2a, const int* __restrict__ e2a)
{
    const int b = blockIdx.x;
    const int t = threadIdx.x;           // 0..191

    const float4* x1_4 = reinterpret_cast<const float4*>(x1);
    const float4* x2_4 = reinterpret_cast<const float4*>(x2);
    float4* f4 = reinterpret_cast<float4*>(g_f);
    const long frow = (long)b * (K4D / 4);   // 768 float4 per sample

    // ---- x1 ----
    {
        int s = s1a[b], e = e1a[b];
        e = max(e, s + 1);
        int lo = max(s, 0), hi = min(e, S);
        int cnt = max(hi - lo, 1);
        float inv = 1.0f / (float)cnt;

        // CLS
        f4[frow + t] = x1_4[((long)b * S + 0) * D4 + t];
        // segment mean
        float4 acc = make_float4(0.f, 0.f, 0.f, 0.f);
        for (int r = lo; r < hi; ++r) {
            float4 v = x1_4[((long)b * S + r) * D4 + t];
            acc.x += v.x; acc.y += v.y; acc.z += v.z; acc.w += v.w;
        }
        acc.x *= inv; acc.y *= inv; acc.z *= inv; acc.w *= inv;
        f4[frow + D4 + t] = acc;
    }
    // ---- x2 ----
    {
        int s = s2a[b], e = e2a[b];
        e = max(e, s + 1);
        int lo = max(s, 0), hi = min(e, S);
        int cnt = max(hi - lo, 1);
        float inv = 1.0f / (float)cnt;

        f4[frow + 2 * D4 + t] = x2_4[((long)b * S + 0) * D4 + t];
        float4 acc = make_float4(0.f, 0.f, 0.f, 0.f);
        for (int r = lo; r < hi; ++r) {
            float4 v = x2_4[((long)b * S + r) * D4 + t];
            acc.x += v.x; acc.y += v.y; acc.z += v.z; acc.w += v.w;
        }
        acc.x *= inv; acc.y *= inv; acc.z *= inv; acc.w *= inv;
        f4[frow + 3 * D4 + t] = acc;
    }
}

// ---------------------------------------------------------------------------
// K2: GEMM1 split-K.  grid = (B/MT, KS), 256 threads (one output column each).
// Writes partial sums (bias folded into split kz==0) to g_h1p[kz].
// ---------------------------------------------------------------------------
__global__ void __launch_bounds__(H1) gemm1_kernel(
    const float* __restrict__ W1, const float* __restrict__ b1)
{
    __shared__ float4 fsh[MT * KC4];      // 16 x 384 floats = 24.5 KB

    const int m0 = blockIdx.x * MT;
    const int kz = blockIdx.y;
    const int k0 = kz * KC;
    const int j  = threadIdx.x;           // output column 0..255

    // Cooperative load of the f tile (float4, coalesced)
    const float4* gf4 = reinterpret_cast<const float4*>(g_f);
    #pragma unroll
    for (int i = 0; i < (MT * KC4) / H1; ++i) {
        int idx = j + i * H1;
        int m = idx / KC4;
        int kv = idx % KC4;
        fsh[idx] = gf4[(long)(m0 + m) * (K4D / 4) + (k0 / 4) + kv];
    }
    __syncthreads();

    float acc[MT];
    #pragma unroll
    for (int m = 0; m < MT; ++m) acc[m] = 0.f;

    const float* w = W1 + (long)k0 * H1 + j;
    #pragma unroll 4
    for (int kv = 0; kv < KC4; ++kv) {
        float w0 = w[(4 * kv + 0) * H1];
        float w1 = w[(4 * kv + 1) * H1];
        float w2 = w[(4 * kv + 2) * H1];
        float w3 = w[(4 * kv + 3) * H1];
        #pragma unroll
        for (int m = 0; m < MT; ++m) {
            float4 fv = fsh[m * KC4 + kv];
            acc[m] = fmaf(fv.x, w0, acc[m]);
            acc[m] = fmaf(fv.y, w1, acc[m]);
            acc[m] = fmaf(fv.z, w2, acc[m]);
            acc[m] = fmaf(fv.w, w3, acc[m]);
        }
    }

    const float bias = (kz == 0) ? b1[j] : 0.f;
    float* outp = g_h1p + (long)kz * (B * H1);
    #pragma unroll
    for (int m = 0; m < MT; ++m)
        outp[(long)(m0 + m) * H1 + j] = acc[m] + bias;
}

// ---------------------------------------------------------------------------
// K3: per-batch fused tail: reduce split-K partials + ReLU -> GEMM2 + ReLU ->
// GEMM3 -> softmax. One block per batch sample, 256 threads.
// ---------------------------------------------------------------------------
__global__ void __launch_bounds__(H1) tail_kernel(
    const float* __restrict__ W2, const float* __restrict__ b2,
    const float* __restrict__ W3, const float* __restrict__ b3,
    float* __restrict__ out)
{
    __shared__ float hsh[H1];
    __shared__ float h2sh[H2];
    __shared__ float lsh[L];

    const int b = blockIdx.x;
    const int t = threadIdx.x;

    // reduce partials + ReLU
    {
        float v = 0.f;
        #pragma unroll
        for (int p = 0; p < KS; ++p)
            v += g_h1p[(long)p * (B * H1) + (long)b * H1 + t];
        hsh[t] = fmaxf(v, 0.f);
    }
    __syncthreads();

    // GEMM2 + ReLU (64 active threads)
    if (t < H2) {
        float acc = b2[t];
        #pragma unroll 8
        for (int k = 0; k < H1; ++k)
            acc = fmaf(hsh[k], W2[k * H2 + t], acc);
        h2sh[t] = fmaxf(acc, 0.f);
    }
    __syncthreads();

    // GEMM3 (4 active threads)
    if (t < L) {
        float acc = b3[t];
        #pragma unroll
        for (int k = 0; k < H2; ++k)
            acc = fmaf(h2sh[k], W3[k * L + t], acc);
        lsh[t] = acc;
    }
    __syncthreads();

    // softmax over L=4 (each of 4 threads recomputes — deterministic)
    if (t < L) {
        float mx = lsh[0];
        #pragma unroll
        for (int l = 1; l < L; ++l) mx = fmaxf(mx, lsh[l]);
        float s = 0.f;
        #pragma unroll
        for (int l = 0; l < L; ++l) s += expf(lsh[l] - mx);
        out[b * L + t] = expf(lsh[t] - mx) / s;
    }
}

// ---------------------------------------------------------------------------
extern "C" void kernel_launch(void* const* d_in, const int* in_sizes, int n_in,
                              void* d_out, int out_size)
{
    const float* x1 = (const float*)d_in[0];
    const float* x2 = (const float*)d_in[1];
    const int*   s1 = (const int*)d_in[2];
    const int*   e1 = (const int*)d_in[3];
    const int*   s2 = (const int*)d_in[4];
    const int*   e2 = (const int*)d_in[5];
    const float* W1 = (const float*)d_in[6];
    const float* b1 = (const float*)d_in[7];
    const float* W2 = (const float*)d_in[8];
    const float* b2 = (const float*)d_in[9];
    const float* W3 = (const float*)d_in[10];
    const float* b3 = (const float*)d_in[11];
    float* out = (float*)d_out;

    feat_kernel<<<B, D4>>>(x1, x2, s1, e1, s2, e2);
    gemm1_kernel<<<dim3(B / MT, KS), H1>>>(W1, b1);
    tail_kernel<<<B, H1>>>(W2, b2, W3, b3, out);
}

// round 2
// speedup vs baseline: 1.3066x; 1.3066x over previous
#include <cuda_runtime.h>
#include <cuda_bf16.h>
#include <math.h>

// Problem constants
#define B   256
#define S   512
#define D   768
#define D4  (D/4)        // 192 float4 per row
#define K4D 3072         // 4*D
#define H1  256
#define H2  64
#define L   4

// GEMM1 tiling
#define BM  32
#define BN  64
#define BK  32
#define KS  8
#define KC  (K4D/KS)     // 384 k per split

// Scratch (device globals — no allocation allowed)
__device__ float g_f[B * K4D];            // features [256, 3072]  (3 MB)
__device__ float g_h1p[KS * B * H1];      // GEMM1 partials [8, 256, 256] (2 MB)

// ---------------------------------------------------------------------------
// packed f32x2 helpers
// ---------------------------------------------------------------------------
__device__ __forceinline__ unsigned long long pack2(float x) {
    unsigned long long r;
    asm("mov.b64 %0, {%1, %1};" : "=l"(r) : "r"(__float_as_uint(x)));
    return r;
}
#define FFMA2(d, a, b) \
    asm("fma.rn.f32x2 %0, %1, %2, %0;" : "+l"(d) : "l"(a), "l"(b))

// ---------------------------------------------------------------------------
// K1: feature extraction. grid (B, 2) — blockIdx.y selects x1/x2.
// 768 threads: col = t%192 (float4 lane), rg = t/192 (4-way row split).
// f[b] = [ CLS(x1) | mean(x1[s1:e1]) | CLS(x2) | mean(x2[s2:e2]) ]
// ---------------------------------------------------------------------------
__global__ void __launch_bounds__(768) feat_kernel(
    const float* __restrict__ x1, const float* __restrict__ x2,
    const int* __restrict__ s1a, const int* __restrict__ e1a,
    const int* __restrict__ s2a, const int* __restrict__ e2a)
{
    __shared__ float4 part[4][D4];        // 12 KB

    const int b   = blockIdx.x;
    const int sel = blockIdx.y;
    const int t   = threadIdx.x;
    const int col = t % D4;
    const int rg  = t / D4;

    const float* x = sel ? x2 : x1;
    int s = sel ? s2a[b] : s1a[b];
    int e = sel ? e2a[b] : e1a[b];
    e = max(e, s + 1);
    int lo = max(s, 0), hi = min(e, S);
    int cnt = max(hi - lo, 1);
    float inv = 1.0f / (float)cnt;

    const float4* x4 = reinterpret_cast<const float4*>(x);
    float4* f4 = reinterpret_cast<float4*>(g_f);
    const long base = (long)b * S * D4;
    const long frow = (long)b * (K4D / 4) + sel * (2 * D4);

    // CLS copy (row group 0)
    if (rg == 0)
        f4[frow + col] = x4[base + col];

    // strided partial sums over the span
    float4 acc = make_float4(0.f, 0.f, 0.f, 0.f);
    for (int r = lo + rg; r < hi; r += 4) {
        float4 v = x4[base + (long)r * D4 + col];
        acc.x += v.x; acc.y += v.y; acc.z += v.z; acc.w += v.w;
    }
    part[rg][col] = acc;
    __syncthreads();

    if (t < D4) {
        float4 a0 = part[0][t], a1 = part[1][t], a2 = part[2][t], a3 = part[3][t];
        float4 o;
        o.x = (a0.x + a1.x + a2.x + a3.x) * inv;
        o.y = (a0.y + a1.y + a2.y + a3.y) * inv;
        o.z = (a0.z + a1.z + a2.z + a3.z) * inv;
        o.w = (a0.w + a1.w + a2.w + a3.w) * inv;
        f4[frow + D4 + t] = o;
    }
}

// ---------------------------------------------------------------------------
// K2: GEMM1 split-K, 32x64 tile, 4x4 micro-tile, packed f32x2 FMA.
// grid (B/BM=8, H1/BN=4, KS=8) = 256 blocks, 128 threads.
// ---------------------------------------------------------------------------
__global__ void __launch_bounds__(128) gemm1_kernel(
    const float* __restrict__ W1, const float* __restrict__ b1)
{
    __shared__ float fsh[BK][BM];         // 4 KB  (k-major so m is contiguous)
    __shared__ float wsh[BK][BN];         // 8 KB

    const int m0 = blockIdx.x * BM;
    const int n0 = blockIdx.y * BN;
    const int kz = blockIdx.z;
    const int k0 = kz * KC;

    const int tid = threadIdx.x;
    const int tx = tid % 16;              // col group: 4 cols each -> 64
    const int ty = tid / 16;              // row group: 4 rows each -> 32

    const float4* gf4 = reinterpret_cast<const float4*>(g_f);
    const float4* w4  = reinterpret_cast<const float4*>(W1);

    // f-tile load indices: kq = float4 slot within BK (8), mrow covers 16 rows x2
    const int kq   = tid % 8;
    const int mrow = tid / 8;
    // w-tile load indices: nq = float4 col slot (16), kr0 covers 8 rows x4
    const int nq  = tid % 16;
    const int kr0 = tid / 16;

    unsigned long long acc2[4][2];
    #pragma unroll
    for (int r = 0; r < 4; ++r) { acc2[r][0] = 0ull; acc2[r][1] = 0ull; }

    for (int kt = 0; kt < KC; kt += BK) {
        // load f tile: BM x BK
        #pragma unroll
        for (int i = 0; i < 2; ++i) {
            int m = mrow + i * 16;
            float4 v = gf4[(long)(m0 + m) * (K4D / 4) + (k0 + kt) / 4 + kq];
            fsh[kq * 4 + 0][m] = v.x;
            fsh[kq * 4 + 1][m] = v.y;
            fsh[kq * 4 + 2][m] = v.z;
            fsh[kq * 4 + 3][m] = v.w;
        }
        // load w tile: BK x BN
        #pragma unroll
        for (int i = 0; i < 4; ++i) {
            int kr = kr0 + i * 8;
            *reinterpret_cast<float4*>(&wsh[kr][nq * 4]) =
                w4[(long)(k0 + kt + kr) * (H1 / 4) + n0 / 4 + nq];
        }
        __syncthreads();

        #pragma unroll
        for (int k = 0; k < BK; ++k) {
            ulonglong2 wp = *reinterpret_cast<const ulonglong2*>(&wsh[k][tx * 4]);
            float4 fv = *reinterpret_cast<const float4*>(&fsh[k][ty * 4]);
            unsigned long long f0 = pack2(fv.x);
            unsigned long long f1 = pack2(fv.y);
            unsigned long long f2 = pack2(fv.z);
            unsigned long long f3 = pack2(fv.w);
            FFMA2(acc2[0][0], f0, wp.x);  FFMA2(acc2[0][1], f0, wp.y);
            FFMA2(acc2[1][0], f1, wp.x);  FFMA2(acc2[1][1], f1, wp.y);
            FFMA2(acc2[2][0], f2, wp.x);  FFMA2(acc2[2][1], f2, wp.y);
            FFMA2(acc2[3][0], f3, wp.x);  FFMA2(acc2[3][1], f3, wp.y);
        }
        __syncthreads();
    }

    // epilogue: unpack, fold bias into split 0, store partials
    float* outp = g_h1p + (long)kz * (B * H1);
    #pragma unroll
    for (int r = 0; r < 4; ++r) {
        int m = m0 + ty * 4 + r;
        #pragma unroll
        for (int p = 0; p < 2; ++p) {
            int n = n0 + tx * 4 + p * 2;
            float lo = __uint_as_float((unsigned)(acc2[r][p] & 0xffffffffull));
            float hi = __uint_as_float((unsigned)(acc2[r][p] >> 32));
            if (kz == 0) { lo += b1[n]; hi += b1[n + 1]; }
            outp[(long)m * H1 + n]     = lo;
            outp[(long)m * H1 + n + 1] = hi;
        }
    }
}

// ---------------------------------------------------------------------------
// K3: per-batch fused tail: reduce split-K partials + ReLU -> GEMM2 + ReLU ->
// GEMM3 -> softmax. One block per batch sample, 256 threads.
// ---------------------------------------------------------------------------
__global__ void __launch_bounds__(H1) tail_kernel(
    const float* __restrict__ W2, const float* __restrict__ b2,
    const float* __restrict__ W3, const float* __restrict__ b3,
    float* __restrict__ out)
{
    __shared__ float hsh[H1];
    __shared__ float p2sh[4][H2];
    __shared__ float h2sh[H2];
    __shared__ float lsh[L];

    const int b = blockIdx.x;
    const int t = threadIdx.x;

    // reduce split-K partials + ReLU
    {
        float v = 0.f;
        #pragma unroll
        for (int p = 0; p < KS; ++p)
            v += g_h1p[(long)p * (B * H1) + (long)b * H1 + t];
        hsh[t] = fmaxf(v, 0.f);
    }
    __syncthreads();

    // GEMM2: 4-way k split, all 256 threads active
    {
        const int j  = t % H2;
        const int kg = t / H2;
        float acc = 0.f;
        #pragma unroll 8
        for (int k = kg * 64; k < (kg + 1) * 64; ++k)
            acc = fmaf(hsh[k], W2[k * H2 + j], acc);
        p2sh[kg][j] = acc;
    }
    __syncthreads();

    if (t < H2) {
        float acc = b2[t] + p2sh[0][t] + p2sh[1][t] + p2sh[2][t] + p2sh[3][t];
        h2sh[t] = fmaxf(acc, 0.f);
    }
    __syncthreads();

    // GEMM3 (tiny: 4 outputs x 64 k)
    if (t < L) {
        float acc = b3[t];
        #pragma unroll
        for (int k = 0; k < H2; ++k)
            acc = fmaf(h2sh[k], W3[k * L + t], acc);
        lsh[t] = acc;
    }
    __syncthreads();

    // softmax over L=4 (each of 4 threads recomputes — deterministic)
    if (t < L) {
        float mx = lsh[0];
        #pragma unroll
        for (int l = 1; l < L; ++l) mx = fmaxf(mx, lsh[l]);
        float s = 0.f;
        #pragma unroll
        for (int l = 0; l < L; ++l) s += expf(lsh[l] - mx);
        out[b * L + t] = expf(lsh[t] - mx) / s;
    }
}

// ---------------------------------------------------------------------------
extern "C" void kernel_launch(void* const* d_in, const int* in_sizes, int n_in,
                              void* d_out, int out_size)
{
    const float* x1 = (const float*)d_in[0];
    const float* x2 = (const float*)d_in[1];
    const int*   s1 = (const int*)d_in[2];
    const int*   e1 = (const int*)d_in[3];
    const int*   s2 = (const int*)d_in[4];
    const int*   e2 = (const int*)d_in[5];
    const float* W1 = (const float*)d_in[6];
    const float* b1 = (const float*)d_in[7];
    const float* W2 = (const float*)d_in[8];
    const float* b2 = (const float*)d_in[9];
    const float* W3 = (const float*)d_in[10];
    const float* b3 = (const float*)d_in[11];
    float* out = (float*)d_out;

    feat_kernel<<<dim3(B, 2), 768>>>(x1, x2, s1, e1, s2, e2);
    gemm1_kernel<<<dim3(B / BM, H1 / BN, KS), 128>>>(W1, b1);
    tail_kernel<<<B, H1>>>(W2, b2, W3, b3, out);
}